// round 17
// baseline (speedup 1.0000x reference)
#include <cuda_runtime.h>
#include <cuda_fp16.h>
#include <math.h>

#define NN   100000
#define EE   1600000
#define FIN  128
#define HIDD 128
#define CC   64
#define EPSV 1e-5f

#define SCAN_B 1024
#define NB_SCAN ((NN + SCAN_B - 1) / SCAN_B)   // 98

// ---------------- scratch (static device globals, no allocation) ----------
__device__ __half g_xw1[(size_t)NN * HIDD];
__device__ __half g_h1 [(size_t)NN * HIDD];   // post-BN+ReLU conv1 out, fp16
__device__ __half g_xw2[(size_t)NN * CC];

__device__ int   g_deg   [NN];
__device__ int   g_off   [NN + 1];
__device__ int   g_cursor[NN];
__device__ int   g_bsum  [NB_SCAN];
__device__ uint2 g_edge  [EE];                 // packed {src, w_bits}
__device__ int   g_mflags[2];

// ---------------- side stream for fork/join inside graph capture ----------
struct SideStream {
    cudaStream_t s;
    cudaEvent_t  evFork, evJoin;
    SideStream() {
        cudaStreamCreateWithFlags(&s, cudaStreamNonBlocking);
        cudaEventCreateWithFlags(&evFork, cudaEventDisableTiming);
        cudaEventCreateWithFlags(&evJoin, cudaEventDisableTiming);
    }
};
static SideStream g_side;

// ---------------------------------------------------------------------------
__device__ __forceinline__ void mma_f16(float* c, const unsigned* a, const unsigned* b) {
    asm volatile(
        "mma.sync.aligned.m16n8k16.row.col.f32.f16.f16.f32 "
        "{%0,%1,%2,%3}, {%4,%5,%6,%7}, {%8,%9}, {%0,%1,%2,%3};"
        : "+f"(c[0]), "+f"(c[1]), "+f"(c[2]), "+f"(c[3])
        : "r"(a[0]), "r"(a[1]), "r"(a[2]), "r"(a[3]), "r"(b[0]), "r"(b[1]));
}

// ---------------------------------------------------------------------------
// Mask dtype detection for BOTH masks in one launch (grid.y = which mask).
// ---------------------------------------------------------------------------
__global__ void mask_detect2_kernel(const unsigned char* __restrict__ p0,
                                    const unsigned char* __restrict__ p1,
                                    int nbytes, int* __restrict__ flags)
{
    const unsigned char* p = blockIdx.y ? p1 : p0;
    int* f = flags + blockIdx.y;
    int i = blockIdx.x * blockDim.x + threadIdx.x;
    if (i >= nbytes) return;
    unsigned char v = p[i];
    if (v) {
        int m = i & 3;
        if (m == 1)      atomicOr(f, 1);
        else if (m >= 2) atomicOr(f, 2);
    }
}

// ---------------------------------------------------------------------------
// CSR build. hist/fill vectorized x4 (EE % 4 == 0).
// ---------------------------------------------------------------------------
__global__ void hist_kernel(const int* __restrict__ dst, int* __restrict__ deg)
{
    int q = blockIdx.x * blockDim.x + threadIdx.x;
    if (q >= EE / 4) return;
    int4 d = ((const int4*)dst)[q];
    atomicAdd(&deg[d.x], 1);
    atomicAdd(&deg[d.y], 1);
    atomicAdd(&deg[d.z], 1);
    atomicAdd(&deg[d.w], 1);
}

__global__ __launch_bounds__(SCAN_B) void scan1_kernel(
    const int* __restrict__ deg, int* __restrict__ off, int* __restrict__ bsum)
{
    __shared__ int s[SCAN_B];
    int i = blockIdx.x * SCAN_B + threadIdx.x;
    int v = (i < NN) ? deg[i] : 0;
    s[threadIdx.x] = v;
    __syncthreads();
    for (int d = 1; d < SCAN_B; d <<= 1) {
        int t = (threadIdx.x >= d) ? s[threadIdx.x - d] : 0;
        __syncthreads();
        s[threadIdx.x] += t;
        __syncthreads();
    }
    if (i < NN) off[i] = s[threadIdx.x] - v;
    if (threadIdx.x == SCAN_B - 1) bsum[blockIdx.x] = s[threadIdx.x];
}

__global__ __launch_bounds__(SCAN_B) void scan23_kernel(
    int* __restrict__ off, int* __restrict__ cursor, const int* __restrict__ bsum)
{
    __shared__ int s_pre;
    if (threadIdx.x == 0) s_pre = 0;
    __syncthreads();
    for (int i = threadIdx.x; i < blockIdx.x; i += blockDim.x)
        atomicAdd(&s_pre, bsum[i]);
    __syncthreads();

    int i = blockIdx.x * SCAN_B + threadIdx.x;
    if (i < NN) {
        int v = off[i] + s_pre;
        off[i]    = v;
        cursor[i] = v;
    }
    if (i == 0) off[NN] = EE;
}

__global__ void fill_kernel(const int* __restrict__ src, const int* __restrict__ dst,
                            const float* __restrict__ ew,
                            int* __restrict__ cursor, uint2* __restrict__ edges)
{
    int q = blockIdx.x * blockDim.x + threadIdx.x;
    if (q >= EE / 4) return;
    int4   s = ((const int4*)src)[q];
    int4   d = ((const int4*)dst)[q];
    float4 w = ((const float4*)ew)[q];
    int p0 = atomicAdd(&cursor[d.x], 1);
    int p1 = atomicAdd(&cursor[d.y], 1);
    int p2 = atomicAdd(&cursor[d.z], 1);
    int p3 = atomicAdd(&cursor[d.w], 1);
    edges[p0] = make_uint2((unsigned)s.x, __float_as_uint(w.x));
    edges[p1] = make_uint2((unsigned)s.y, __float_as_uint(w.y));
    edges[p2] = make_uint2((unsigned)s.z, __float_as_uint(w.z));
    edges[p3] = make_uint2((unsigned)s.w, __float_as_uint(w.w));
}

// ---------------------------------------------------------------------------
// GEMM1 (fp16 MMA, fp32 acc): Y[N,128](half) = X[N,128] @ W[128,128]
// ---------------------------------------------------------------------------
#define XS_STRIDE 136
__global__ __launch_bounds__(256) void gemm1_tc_kernel(
    const float* __restrict__ X, const float* __restrict__ W,
    __half* __restrict__ Y, int n)
{
    __shared__ __half xs [128][XS_STRIDE];
    __shared__ __half wsT[128][XS_STRIDE];

    const int t    = threadIdx.x;
    const int w    = t >> 5;
    const int lane = t & 31;
    const int g    = lane >> 2;
    const int tg   = lane & 3;
    const int wr   = w >> 1;
    const int wc   = w & 1;
    const int row0 = blockIdx.x * 128;

#pragma unroll
    for (int it = 0; it < 16; it++) {
        int idx = t + it * 256;
        int r   = idx >> 5;
        int c4  = (idx & 31) * 4;
        int gr  = row0 + r; if (gr >= n) gr = n - 1;
        float4 xv = *(const float4*)(X + (size_t)gr * 128 + c4);
        *(__half2*)&xs[r][c4]     = __floats2half2_rn(xv.x, xv.y);
        *(__half2*)&xs[r][c4 + 2] = __floats2half2_rn(xv.z, xv.w);
    }
    {
        int nn = t & 127;
        int k0 = (t >> 7) * 2;
        for (int kk = k0; kk < 128; kk += 4) {
            float w0 = W[(size_t)kk       * 128 + nn];
            float w1 = W[(size_t)(kk + 1) * 128 + nn];
            *(__half2*)&wsT[nn][kk] = __floats2half2_rn(w0, w1);
        }
    }
    __syncthreads();

    float acc[2][8][4];
#pragma unroll
    for (int mi = 0; mi < 2; mi++)
#pragma unroll
        for (int j = 0; j < 8; j++)
#pragma unroll
            for (int q = 0; q < 4; q++) acc[mi][j][q] = 0.f;

#pragma unroll
    for (int k0 = 0; k0 < 128; k0 += 16) {
        unsigned a[2][4];
#pragma unroll
        for (int mi = 0; mi < 2; mi++) {
            const int r0 = wr * 32 + mi * 16 + g;
            a[mi][0] = *(const unsigned*)&xs[r0    ][k0 + 2 * tg    ];
            a[mi][1] = *(const unsigned*)&xs[r0 + 8][k0 + 2 * tg    ];
            a[mi][2] = *(const unsigned*)&xs[r0    ][k0 + 2 * tg + 8];
            a[mi][3] = *(const unsigned*)&xs[r0 + 8][k0 + 2 * tg + 8];
        }
#pragma unroll
        for (int j = 0; j < 8; j++) {
            const int col = wc * 64 + 8 * j + g;
            unsigned b[2];
            b[0] = *(const unsigned*)&wsT[col][k0 + 2 * tg    ];
            b[1] = *(const unsigned*)&wsT[col][k0 + 2 * tg + 8];
            mma_f16(acc[0][j], a[0], b);
            mma_f16(acc[1][j], a[1], b);
        }
    }

#pragma unroll
    for (int mi = 0; mi < 2; mi++) {
        const int r0g = row0 + wr * 32 + mi * 16 + g;
        const int r1g = r0g + 8;
#pragma unroll
        for (int j = 0; j < 8; j++) {
            const int c2 = wc * 32 + j * 4 + tg;
            if (r0g < n)
                ((__half2*)(Y + (size_t)r0g * 128))[c2] =
                    __floats2half2_rn(acc[mi][j][0], acc[mi][j][1]);
            if (r1g < n)
                ((__half2*)(Y + (size_t)r1g * 128))[c2] =
                    __floats2half2_rn(acc[mi][j][2], acc[mi][j][3]);
        }
    }
}

// ---------------------------------------------------------------------------
// GEMM2 (fp16 MMA): Y[N,64](half) = H1h[N,128](half) @ W2[128,64]
// ---------------------------------------------------------------------------
__global__ __launch_bounds__(256) void gemm2_tc_kernel(
    const __half* __restrict__ H1h, const float* __restrict__ W2,
    __half* __restrict__ Y, int n)
{
    __shared__ __half xs [128][XS_STRIDE];
    __shared__ __half wsT[64][XS_STRIDE];

    const int t    = threadIdx.x;
    const int w    = t >> 5;
    const int lane = t & 31;
    const int g    = lane >> 2;
    const int tg   = lane & 3;
    const int wr   = w >> 1;
    const int wc   = w & 1;
    const int row0 = blockIdx.x * 128;

#pragma unroll
    for (int it = 0; it < 8; it++) {
        int idx = t + it * 256;
        int r   = idx >> 4;
        int c8  = (idx & 15) * 8;
        int gr  = row0 + r; if (gr >= n) gr = n - 1;
        uint4 v = *(const uint4*)(H1h + (size_t)gr * 128 + c8);
        *(uint4*)&xs[r][c8] = v;
    }
    {
        int nn = t & 63;
        int k0 = (t >> 6) * 2;
        for (int kk = k0; kk < 128; kk += 8) {
            float w0 = W2[(size_t)kk       * 64 + nn];
            float w1 = W2[(size_t)(kk + 1) * 64 + nn];
            *(__half2*)&wsT[nn][kk] = __floats2half2_rn(w0, w1);
        }
    }
    __syncthreads();

    float acc[2][4][4];
#pragma unroll
    for (int mi = 0; mi < 2; mi++)
#pragma unroll
        for (int j = 0; j < 4; j++)
#pragma unroll
            for (int q = 0; q < 4; q++) acc[mi][j][q] = 0.f;

#pragma unroll
    for (int k0 = 0; k0 < 128; k0 += 16) {
        unsigned a[2][4];
#pragma unroll
        for (int mi = 0; mi < 2; mi++) {
            const int r0 = wr * 32 + mi * 16 + g;
            a[mi][0] = *(const unsigned*)&xs[r0    ][k0 + 2 * tg    ];
            a[mi][1] = *(const unsigned*)&xs[r0 + 8][k0 + 2 * tg    ];
            a[mi][2] = *(const unsigned*)&xs[r0    ][k0 + 2 * tg + 8];
            a[mi][3] = *(const unsigned*)&xs[r0 + 8][k0 + 2 * tg + 8];
        }
#pragma unroll
        for (int j = 0; j < 4; j++) {
            const int col = wc * 32 + 8 * j + g;
            unsigned b[2];
            b[0] = *(const unsigned*)&wsT[col][k0 + 2 * tg    ];
            b[1] = *(const unsigned*)&wsT[col][k0 + 2 * tg + 8];
            mma_f16(acc[0][j], a[0], b);
            mma_f16(acc[1][j], a[1], b);
        }
    }

#pragma unroll
    for (int mi = 0; mi < 2; mi++) {
        const int r0g = row0 + wr * 32 + mi * 16 + g;
        const int r1g = r0g + 8;
#pragma unroll
        for (int j = 0; j < 4; j++) {
            const int c2 = wc * 16 + j * 4 + tg;
            if (r0g < n)
                ((__half2*)(Y + (size_t)r0g * 64))[c2] =
                    __floats2half2_rn(acc[mi][j][0], acc[mi][j][1]);
            if (r1g < n)
                ((__half2*)(Y + (size_t)r1g * 64))[c2] =
                    __floats2half2_rn(acc[mi][j][2], acc[mi][j][3]);
        }
    }
}

// ---------------------------------------------------------------------------
// Aggregation 1 + BN + ReLU, fp16 out. Warp per node; HALF-WARP per edge
// (lane loads uint4 = 8 features). 4 edges per iteration, 2 LDG.128/lane.
// Tile padded with weight-0 records so no tail code is needed.
// ---------------------------------------------------------------------------
__global__ __launch_bounds__(256) void agg1_kernel(
    const int* __restrict__ off, const uint2* __restrict__ edges,
    const __half* __restrict__ xw,
    const float* __restrict__ b1, const float* __restrict__ gamma,
    const float* __restrict__ beta, const float* __restrict__ mean,
    const float* __restrict__ var,
    __half* __restrict__ h)
{
    __shared__ uint2 tile[8][32];

    const int w    = threadIdx.x >> 5;
    const int lane = threadIdx.x & 31;
    const int half = lane >> 4;     // which edge of the pair
    const int cidx = lane & 15;     // uint4 chunk within 256B row
    const int r    = blockIdx.x * 8 + w;
    if (r >= NN) return;

    const int start = off[r];
    const int end   = off[r + 1];

    float2 a0 = {0.f, 0.f}, a1 = {0.f, 0.f}, a2 = {0.f, 0.f}, a3 = {0.f, 0.f};

    for (int base = start; base < end; base += 32) {
        int rem = end - base;
        int cnt = rem < 32 ? rem : 32;
        tile[w][lane] = (lane < cnt) ? edges[base + lane] : make_uint2(0u, 0u);
        __syncwarp();
        for (int j = 0; j < cnt; j += 4) {
            uint2 ea = tile[w][j + half];
            uint2 eb = tile[w][j + 2 + half];
            uint4 qa = ((const uint4*)(xw + (size_t)ea.x * 128))[cidx];
            uint4 qb = ((const uint4*)(xw + (size_t)eb.x * 128))[cidx];
            float wa = __uint_as_float(ea.y);
            float wb = __uint_as_float(eb.y);
            {
                float2 f0 = __half22float2(*(__half2*)&qa.x);
                float2 f1 = __half22float2(*(__half2*)&qa.y);
                float2 f2 = __half22float2(*(__half2*)&qa.z);
                float2 f3 = __half22float2(*(__half2*)&qa.w);
                a0.x = fmaf(wa, f0.x, a0.x); a0.y = fmaf(wa, f0.y, a0.y);
                a1.x = fmaf(wa, f1.x, a1.x); a1.y = fmaf(wa, f1.y, a1.y);
                a2.x = fmaf(wa, f2.x, a2.x); a2.y = fmaf(wa, f2.y, a2.y);
                a3.x = fmaf(wa, f3.x, a3.x); a3.y = fmaf(wa, f3.y, a3.y);
            }
            {
                float2 f0 = __half22float2(*(__half2*)&qb.x);
                float2 f1 = __half22float2(*(__half2*)&qb.y);
                float2 f2 = __half22float2(*(__half2*)&qb.z);
                float2 f3 = __half22float2(*(__half2*)&qb.w);
                a0.x = fmaf(wb, f0.x, a0.x); a0.y = fmaf(wb, f0.y, a0.y);
                a1.x = fmaf(wb, f1.x, a1.x); a1.y = fmaf(wb, f1.y, a1.y);
                a2.x = fmaf(wb, f2.x, a2.x); a2.y = fmaf(wb, f2.y, a2.y);
                a3.x = fmaf(wb, f3.x, a3.x); a3.y = fmaf(wb, f3.y, a3.y);
            }
        }
        __syncwarp();
    }

    // merge halves (lane L and L^16 hold same feature chunk)
    a0.x += __shfl_xor_sync(0xffffffffu, a0.x, 16);
    a0.y += __shfl_xor_sync(0xffffffffu, a0.y, 16);
    a1.x += __shfl_xor_sync(0xffffffffu, a1.x, 16);
    a1.y += __shfl_xor_sync(0xffffffffu, a1.y, 16);
    a2.x += __shfl_xor_sync(0xffffffffu, a2.x, 16);
    a2.y += __shfl_xor_sync(0xffffffffu, a2.y, 16);
    a3.x += __shfl_xor_sync(0xffffffffu, a3.x, 16);
    a3.y += __shfl_xor_sync(0xffffffffu, a3.y, 16);

    // BN + ReLU on features cidx*8 .. cidx*8+7
    const int f = cidx * 8;
    float4 gm0 = *(const float4*)(gamma + f);
    float4 gm1 = *(const float4*)(gamma + f + 4);
    float4 vr0 = *(const float4*)(var   + f);
    float4 vr1 = *(const float4*)(var   + f + 4);
    float4 mn0 = *(const float4*)(mean  + f);
    float4 mn1 = *(const float4*)(mean  + f + 4);
    float4 bt0 = *(const float4*)(beta  + f);
    float4 bt1 = *(const float4*)(beta  + f + 4);
    float4 bb0 = *(const float4*)(b1    + f);
    float4 bb1 = *(const float4*)(b1    + f + 4);

    float v0 = fmaxf(fmaf(a0.x + bb0.x - mn0.x, gm0.x * rsqrtf(vr0.x + EPSV), bt0.x), 0.f);
    float v1 = fmaxf(fmaf(a0.y + bb0.y - mn0.y, gm0.y * rsqrtf(vr0.y + EPSV), bt0.y), 0.f);
    float v2 = fmaxf(fmaf(a1.x + bb0.z - mn0.z, gm0.z * rsqrtf(vr0.z + EPSV), bt0.z), 0.f);
    float v3 = fmaxf(fmaf(a1.y + bb0.w - mn0.w, gm0.w * rsqrtf(vr0.w + EPSV), bt0.w), 0.f);
    float v4 = fmaxf(fmaf(a2.x + bb1.x - mn1.x, gm1.x * rsqrtf(vr1.x + EPSV), bt1.x), 0.f);
    float v5 = fmaxf(fmaf(a2.y + bb1.y - mn1.y, gm1.y * rsqrtf(vr1.y + EPSV), bt1.y), 0.f);
    float v6 = fmaxf(fmaf(a3.x + bb1.z - mn1.z, gm1.z * rsqrtf(vr1.z + EPSV), bt1.z), 0.f);
    float v7 = fmaxf(fmaf(a3.y + bb1.w - mn1.w, gm1.w * rsqrtf(vr1.w + EPSV), bt1.w), 0.f);

    if (half == 0) {
        uint4 outv;
        *(__half2*)&outv.x = __floats2half2_rn(v0, v1);
        *(__half2*)&outv.y = __floats2half2_rn(v2, v3);
        *(__half2*)&outv.z = __floats2half2_rn(v4, v5);
        *(__half2*)&outv.w = __floats2half2_rn(v6, v7);
        ((uint4*)(h + (size_t)r * 128))[cidx] = outv;
    }
}

// ---------------------------------------------------------------------------
// Fused: aggregation 2 + bias + combine + log_softmax.
// Warp per node; QUARTER-WARP per edge (lane loads uint4 = 8 features of the
// 64-dim row). 16 edges per iteration, 4 LDG.128/lane.
// ---------------------------------------------------------------------------
__global__ __launch_bounds__(256) void agg2_combine_kernel(
    const int* __restrict__ off, const uint2* __restrict__ edges,
    const __half* __restrict__ xw,
    const float* __restrict__ b2, const float* __restrict__ prev,
    const void* __restrict__ sens_raw, const void* __restrict__ insens_raw,
    const int* __restrict__ mflags,
    float* __restrict__ out_logsm, float* __restrict__ out_raw)
{
    __shared__ uint2 tile[8][32];

    const int w    = threadIdx.x >> 5;
    const int lane = threadIdx.x & 31;
    const int qid  = lane >> 3;     // quarter id: which edge of group of 4
    const int cidx = lane & 7;      // uint4 chunk within 128B row
    const int r    = blockIdx.x * 8 + w;
    if (r >= NN) return;

    const int start = off[r];
    const int end   = off[r + 1];

    float2 a0 = {0.f, 0.f}, a1 = {0.f, 0.f}, a2 = {0.f, 0.f}, a3 = {0.f, 0.f};

    for (int base = start; base < end; base += 32) {
        int rem = end - base;
        int cnt = rem < 32 ? rem : 32;
        tile[w][lane] = (lane < cnt) ? edges[base + lane] : make_uint2(0u, 0u);
        __syncwarp();
        for (int j = 0; j < cnt; j += 16) {
            uint2 ea = tile[w][j + qid];
            uint2 eb = tile[w][j + 4 + qid];
            uint2 ec = tile[w][j + 8 + qid];
            uint2 ed = tile[w][j + 12 + qid];
            uint4 qa = ((const uint4*)(xw + (size_t)ea.x * 64))[cidx];
            uint4 qb = ((const uint4*)(xw + (size_t)eb.x * 64))[cidx];
            uint4 qc = ((const uint4*)(xw + (size_t)ec.x * 64))[cidx];
            uint4 qd = ((const uint4*)(xw + (size_t)ed.x * 64))[cidx];
            float wa = __uint_as_float(ea.y);
            float wb = __uint_as_float(eb.y);
            float wc = __uint_as_float(ec.y);
            float wd = __uint_as_float(ed.y);
#define ACC8(q, wt) { \
            float2 f0 = __half22float2(*(__half2*)&(q).x); \
            float2 f1 = __half22float2(*(__half2*)&(q).y); \
            float2 f2 = __half22float2(*(__half2*)&(q).z); \
            float2 f3 = __half22float2(*(__half2*)&(q).w); \
            a0.x = fmaf(wt, f0.x, a0.x); a0.y = fmaf(wt, f0.y, a0.y); \
            a1.x = fmaf(wt, f1.x, a1.x); a1.y = fmaf(wt, f1.y, a1.y); \
            a2.x = fmaf(wt, f2.x, a2.x); a2.y = fmaf(wt, f2.y, a2.y); \
            a3.x = fmaf(wt, f3.x, a3.x); a3.y = fmaf(wt, f3.y, a3.y); }
            ACC8(qa, wa)
            ACC8(qb, wb)
            ACC8(qc, wc)
            ACC8(qd, wd)
#undef ACC8
        }
        __syncwarp();
    }

    // merge quarters (lanes with same cidx differ in bits 3,4)
#define MERGE(x) x += __shfl_xor_sync(0xffffffffu, x, 8); \
                 x += __shfl_xor_sync(0xffffffffu, x, 16);
    MERGE(a0.x) MERGE(a0.y) MERGE(a1.x) MERGE(a1.y)
    MERGE(a2.x) MERGE(a2.y) MERGE(a3.x) MERGE(a3.y)
#undef MERGE

    // bias + combine on features cidx*8 .. +7
    const int f = cidx * 8;
    float4 bb0 = *(const float4*)(b2 + f);
    float4 bb1 = *(const float4*)(b2 + f + 4);
    float h0 = a0.x + bb0.x, h1 = a0.y + bb0.y;
    float h2 = a1.x + bb0.z, h3 = a1.y + bb0.w;
    float h4 = a2.x + bb1.x, h5 = a2.y + bb1.y;
    float h6 = a3.x + bb1.z, h7 = a3.y + bb1.w;

    int fs = mflags[0], fi = mflags[1];
    bool sv = (fs & 1) ? (((const unsigned char*)sens_raw)[r] != 0)
            : (fs & 2) ? (((const float*)sens_raw)[r] != 0.0f)
                       : (((const int*)sens_raw)[r] != 0);
    bool iv = (fi & 1) ? (((const unsigned char*)insens_raw)[r] != 0)
            : (fi & 2) ? (((const float*)insens_raw)[r] != 0.0f)
                       : (((const int*)insens_raw)[r] != 0);

    float4 pv0 = *(const float4*)(prev + (size_t)r * 64 + f);
    float4 pv1 = *(const float4*)(prev + (size_t)r * 64 + f + 4);
    float o0 = (sv ? h0 : pv0.x) + (iv ? h0 : 0.f);
    float o1 = (sv ? h1 : pv0.y) + (iv ? h1 : 0.f);
    float o2 = (sv ? h2 : pv0.z) + (iv ? h2 : 0.f);
    float o3 = (sv ? h3 : pv0.w) + (iv ? h3 : 0.f);
    float o4 = (sv ? h4 : pv1.x) + (iv ? h4 : 0.f);
    float o5 = (sv ? h5 : pv1.y) + (iv ? h5 : 0.f);
    float o6 = (sv ? h6 : pv1.z) + (iv ? h6 : 0.f);
    float o7 = (sv ? h7 : pv1.w) + (iv ? h7 : 0.f);

    // log-softmax over all 64 features: butterfly within 8-lane chunk groups
    float m = fmaxf(fmaxf(fmaxf(o0, o1), fmaxf(o2, o3)),
                    fmaxf(fmaxf(o4, o5), fmaxf(o6, o7)));
#pragma unroll
    for (int offd = 1; offd <= 4; offd <<= 1)
        m = fmaxf(m, __shfl_xor_sync(0xffffffffu, m, offd));
    float s = __expf(o0 - m) + __expf(o1 - m) + __expf(o2 - m) + __expf(o3 - m)
            + __expf(o4 - m) + __expf(o5 - m) + __expf(o6 - m) + __expf(o7 - m);
#pragma unroll
    for (int offd = 1; offd <= 4; offd <<= 1)
        s += __shfl_xor_sync(0xffffffffu, s, offd);
    float lse = m + logf(s);

    if (qid == 0) {
        float4 w0 = {o0 - lse, o1 - lse, o2 - lse, o3 - lse};
        float4 w1 = {o4 - lse, o5 - lse, o6 - lse, o7 - lse};
        *(float4*)(out_logsm + (size_t)r * 64 + f)     = w0;
        *(float4*)(out_logsm + (size_t)r * 64 + f + 4) = w1;
        if (out_raw) {
            float4 r0 = {o0, o1, o2, o3};
            float4 r1 = {o4, o5, o6, o7};
            *(float4*)(out_raw + (size_t)r * 64 + f)     = r0;
            *(float4*)(out_raw + (size_t)r * 64 + f + 4) = r1;
        }
    }
}

// ---------------------------------------------------------------------------
extern "C" void kernel_launch(void* const* d_in, const int* in_sizes, int n_in,
                              void* d_out, int out_size)
{
    const float* features = (const float*)d_in[0];
    const int*   edge_src = (const int*)  d_in[1];
    const int*   edge_dst = (const int*)  d_in[2];
    const float* edge_w   = (const float*)d_in[3];
    const float* W1       = (const float*)d_in[4];
    const float* b1       = (const float*)d_in[5];
    const float* gamma1   = (const float*)d_in[6];
    const float* beta1    = (const float*)d_in[7];
    const float* mean1    = (const float*)d_in[8];
    const float* var1     = (const float*)d_in[9];
    const float* W2       = (const float*)d_in[10];
    const float* b2       = (const float*)d_in[11];
    const float* emb_prev = (const float*)d_in[12];
    const void*  sens_raw   = d_in[13];
    const void*  insens_raw = d_in[14];

    __half* xw1; cudaGetSymbolAddress((void**)&xw1, g_xw1);
    __half* h1;  cudaGetSymbolAddress((void**)&h1,  g_h1);
    __half* xw2; cudaGetSymbolAddress((void**)&xw2, g_xw2);
    int*   deg;    cudaGetSymbolAddress((void**)&deg,    g_deg);
    int*   off;    cudaGetSymbolAddress((void**)&off,    g_off);
    int*   cursor; cudaGetSymbolAddress((void**)&cursor, g_cursor);
    int*   bsum;   cudaGetSymbolAddress((void**)&bsum,   g_bsum);
    uint2* edges;  cudaGetSymbolAddress((void**)&edges,  g_edge);
    int*   mflags; cudaGetSymbolAddress((void**)&mflags, g_mflags);

    const int QB = (EE / 4 + 255) / 256;
    const int MB = (NN + 255) / 256;
    cudaStream_t s1 = g_side.s;

    cudaMemsetAsync(deg, 0, NN * sizeof(int), 0);
    cudaMemsetAsync(mflags, 0, 2 * sizeof(int), 0);

    // FORK: side stream runs GEMM1 + mask sniff concurrently with CSR build
    cudaEventRecord(g_side.evFork, 0);
    cudaStreamWaitEvent(s1, g_side.evFork, 0);

    gemm1_tc_kernel<<<(NN + 127) / 128, 256, 0, s1>>>(features, W1, xw1, NN);    // k1
    {
        dim3 mg(MB, 2);
        mask_detect2_kernel<<<mg, 256, 0, s1>>>(
            (const unsigned char*)sens_raw, (const unsigned char*)insens_raw,
            NN, mflags);                                                          // k2
    }
    cudaEventRecord(g_side.evJoin, s1);

    // Origin stream: CSR build chain
    hist_kernel<<<QB, 256>>>(edge_dst, deg);                                      // k3
    scan1_kernel<<<NB_SCAN, SCAN_B>>>(deg, off, bsum);                            // k4 (profiled)
    scan23_kernel<<<NB_SCAN, SCAN_B>>>(off, cursor, bsum);                        // k5
    fill_kernel<<<QB, 256>>>(edge_src, edge_dst, edge_w, cursor, edges);          // k6

    // JOIN: origin needs gemm1 (xw1) + masks before agg tail
    cudaStreamWaitEvent(0, g_side.evJoin, 0);

    agg1_kernel<<<(NN + 7) / 8, 256>>>(off, edges, xw1,
                                       b1, gamma1, beta1, mean1, var1, h1);       // k7
    gemm2_tc_kernel<<<(NN + 127) / 128, 256>>>(h1, W2, xw2, NN);                  // k8
    {
        float* outp = (float*)d_out;
        float* rawp = (out_size >= 2 * NN * CC) ? (outp + (size_t)NN * CC) : (float*)0;
        agg2_combine_kernel<<<(NN + 7) / 8, 256>>>(
            off, edges, xw2, b2, emb_prev, sens_raw, insens_raw, mflags,
            outp, rawp);                                                          // k9
    }
}